// round 9
// baseline (speedup 1.0000x reference)
#include <cuda_runtime.h>
#include <cstdint>

// DepthDeformConv: modulated deformable conv 3x3, s=1, p=1, d=1.
// B=4, C=64, H=W=128, O=64, K=9, fp32. Output (4,64,128,128) fp32.
//
// K0 (k_nhwc): repack input NCHW -> NHWC8: g_in8[b][g][y*128+x][8].
// K1 (k_prep): permute weights: g_wt[(cc*72 + k*8 + cl)*64 + o].
// K2 (ddc_main): one block per (b,y); 256 threads; 3 blocks/SM
//   (smem 64.5KB, <=85 regs). Phases alternate per chunk; inter-block
//   overlap (3 resident blocks) hides phase serialization.
//   - META (once): 1152 (k,pix) jobs -> short4 indices + float4 fused weights
//   - per chunk cc (8 chunks of 8 channels = 72 col rows):
//       gather: 4-lane groups (lane = ch pair), 4 x LDG.64 dense taps,
//               2 STS.32 into XOR-swizzled col (conflict-free)
//       FMA: warp = 8 outputs x 128 pix, full-K accum in regs; weights via
//            uniform __ldg (L1-resident); fma.rn.f32x2 pairs
//   - epilogue: bias + STG.128 (no reduction).

#define HW 128
#define PLANE 16384
#define CIN 64
#define OOUT 64
#define CKTOT 576
#define NJOBS 1152
#define RPC 72
#define NCHUNK 8
#define NTHREADS 256

#define OFF_MI 36864                    // col: [0, 36864)
#define OFF_MW (OFF_MI + 9216)          // 46080
#define SMEM_TOTAL (OFF_MW + 18432)     // 64512

typedef unsigned long long ull;

__device__ float g_in8[4 * 8 * PLANE * 8];   // 16 MB
__device__ float g_wt[CKTOT * OOUT];

__device__ __forceinline__ ull pack2(float lo, float hi) {
    ull d;
    asm("mov.b64 %0, {%1, %2};" : "=l"(d) : "f"(lo), "f"(hi));
    return d;
}
__device__ __forceinline__ float2 unpack2(ull v) {
    float2 r;
    asm("mov.b64 {%0, %1}, %2;" : "=f"(r.x), "=f"(r.y) : "l"(v));
    return r;
}
__device__ __forceinline__ ull fma2(ull a, ull b, ull c) {
    ull d;
    asm("fma.rn.f32x2 %0, %1, %2, %3;" : "=l"(d) : "l"(a), "l"(b), "l"(c));
    return d;
}

// ---------------- K0: NCHW -> NHWC8 ----------------
__global__ __launch_bounds__(256) void k_nhwc(const float* __restrict__ in) {
    __shared__ float t[64][129];
    const int bid = blockIdx.x;
    const int y = bid & 127, b = bid >> 7;
    const int tid = threadIdx.x;
    const float* ib = in + (size_t)b * CIN * PLANE + y * HW;
    #pragma unroll 8
    for (int it = 0; it < 32; it++) {
        int i = tid + it * 256;
        int c = i >> 7, x = i & 127;
        t[c][x] = __ldg(ib + c * PLANE + x);
    }
    __syncthreads();
    #pragma unroll 8
    for (int it = 0; it < 32; it++) {
        int i = tid + it * 256;
        int cl = i & 7, x = (i >> 3) & 127, g = i >> 10;
        g_in8[(((size_t)(b * 8 + g)) * PLANE + y * HW + x) * 8 + cl] = t[g * 8 + cl][x];
    }
}

// ---------------- K1: weight permute ----------------
__global__ __launch_bounds__(256) void k_prep(const float* __restrict__ w) {
    int idx = blockIdx.x * 256 + threadIdx.x;
    if (idx >= OOUT * CKTOT) return;
    int o = idx / CKTOT, rem = idx - o * CKTOT;
    int c = rem / 9, k = rem - c * 9;
    int cc = c >> 3, cl = c & 7;
    g_wt[(cc * RPC + k * 8 + cl) * OOUT + o] = w[idx];
}

// ---------------- K2: main ----------------
extern __shared__ char smraw[];

__global__ __launch_bounds__(NTHREADS, 3)
void ddc_main(const float* __restrict__ offset,
              const float* __restrict__ mask,
              const float* __restrict__ bias,
              float* __restrict__ out)
{
    float*  col    = (float*)smraw;              // [72][128] swizzled
    short4* meta_i = (short4*)(smraw + OFF_MI);
    float4* meta_w = (float4*)(smraw + OFF_MW);

    const int tid = threadIdx.x;
    const int bid = blockIdx.x;
    const int y = bid & 127;
    const int b = bid >> 7;
    const int wid  = tid >> 5;
    const int lane = tid & 31;
    const int og   = wid;          // o-group: 8 outputs, o base = og*8
    const int grp  = tid >> 2;     // gather group 0..63
    const int p    = tid & 3;      // channel pair within group

    // ---- META: 1152 jobs, once per block ----
    for (int i = tid; i < NJOBS; i += NTHREADS) {
        int pix = i & 127;
        int k   = i >> 7;
        int ky  = k / 3;
        int kx  = k - ky * 3;

        int ob = ((b * 18 + 2 * k) * HW + y) * HW + pix;
        float oy = __ldg(offset + ob);
        float ox = __ldg(offset + ob + PLANE);
        float m  = __ldg(mask + ((b * 9 + k) * HW + y) * HW + pix);

        float py = (float)(y - 1 + ky) + oy;
        float px = (float)(pix - 1 + kx) + ox;
        float y0f = floorf(py), x0f = floorf(px);
        int y0 = (int)y0f, x0 = (int)x0f;
        float wy = py - y0f, wx = px - x0f;
        int y1 = y0 + 1, x1 = x0 + 1;

        float vy0 = (y0 >= 0 && y0 < HW) ? 1.f : 0.f;
        float vy1 = (y1 >= 0 && y1 < HW) ? 1.f : 0.f;
        float vx0 = (x0 >= 0 && x0 < HW) ? 1.f : 0.f;
        float vx1 = (x1 >= 0 && x1 < HW) ? 1.f : 0.f;
        int yc0 = min(max(y0, 0), HW - 1);
        int yc1 = min(max(y1, 0), HW - 1);
        int xc0 = min(max(x0, 0), HW - 1);
        int xc1 = min(max(x1, 0), HW - 1);

        float4 w;
        w.x = (1.f - wy) * (1.f - wx) * m * vy0 * vx0;
        w.y = (1.f - wy) * wx         * m * vy0 * vx1;
        w.z = wy         * (1.f - wx) * m * vy1 * vx0;
        w.w = wy         * wx         * m * vy1 * vx1;

        meta_i[i] = make_short4((short)(yc0 * HW + xc0), (short)(yc0 * HW + xc1),
                                (short)(yc1 * HW + xc0), (short)(yc1 * HW + xc1));
        meta_w[i] = w;
    }

    // acc[j][q]: o-pair j (o = og*8 + 2j, +2j+1), pixel q (pix = lane*4+q)
    ull acc[4][4];
    #pragma unroll
    for (int j = 0; j < 4; j++)
        #pragma unroll
        for (int q = 0; q < 4; q++) acc[j][q] = 0ULL;

    for (int cc = 0; cc < NCHUNK; cc++) {
        __syncthreads();    // meta ready / previous FMA done with col

        // ---- gather: 1152 jobs x 4 lanes; 18 iters/thread ----
        const float2* nb = (const float2*)g_in8 + ((size_t)(b * 8 + cc)) * PLANE * 4;
        #pragma unroll 2
        for (int j = grp; j < NJOBS; j += 64) {
            short4 mi = meta_i[j];
            float4 mw = meta_w[j];
            float2 t00 = __ldg(nb + ((int)mi.x << 2) + p);
            float2 t01 = __ldg(nb + ((int)mi.y << 2) + p);
            float2 t10 = __ldg(nb + ((int)mi.z << 2) + p);
            float2 t11 = __ldg(nb + ((int)mi.w << 2) + p);

            float vx_ = mw.x * t00.x + mw.y * t01.x + mw.z * t10.x + mw.w * t11.x;
            float vy_ = mw.x * t00.y + mw.y * t01.y + mw.z * t10.y + mw.w * t11.y;

            int r   = (j >> 7) * 8 + 2 * p;    // k*8 + 2p
            int psw = (j & 127) ^ (p << 3);
            col[r * HW + psw]       = vx_;
            col[(r + 1) * HW + psw] = vy_;
        }
        __syncthreads();

        // ---- FMA: all 72 rows, 8 outputs x 4 pix per thread ----
        const float4* wbase = (const float4*)(g_wt + (size_t)cc * RPC * OOUT + og * 8);
        #pragma unroll 4
        for (int row = 0; row < RPC; row++) {
            int sw = (((unsigned)row >> 1) & 3) << 3;
            float4 cq = *(const float4*)(col + row * HW + ((lane * 4) ^ sw));
            ull cp0 = pack2(cq.x, cq.x);
            ull cp1 = pack2(cq.y, cq.y);
            ull cp2 = pack2(cq.z, cq.z);
            ull cp3 = pack2(cq.w, cq.w);
            float4 wq0 = __ldg(wbase + row * 16);       // o pairs 0,1
            float4 wq1 = __ldg(wbase + row * 16 + 1);   // o pairs 2,3
            ull wp0 = pack2(wq0.x, wq0.y);
            ull wp1 = pack2(wq0.z, wq0.w);
            ull wp2 = pack2(wq1.x, wq1.y);
            ull wp3 = pack2(wq1.z, wq1.w);
            acc[0][0] = fma2(wp0, cp0, acc[0][0]);
            acc[0][1] = fma2(wp0, cp1, acc[0][1]);
            acc[0][2] = fma2(wp0, cp2, acc[0][2]);
            acc[0][3] = fma2(wp0, cp3, acc[0][3]);
            acc[1][0] = fma2(wp1, cp0, acc[1][0]);
            acc[1][1] = fma2(wp1, cp1, acc[1][1]);
            acc[1][2] = fma2(wp1, cp2, acc[1][2]);
            acc[1][3] = fma2(wp1, cp3, acc[1][3]);
            acc[2][0] = fma2(wp2, cp0, acc[2][0]);
            acc[2][1] = fma2(wp2, cp1, acc[2][1]);
            acc[2][2] = fma2(wp2, cp2, acc[2][2]);
            acc[2][3] = fma2(wp2, cp3, acc[2][3]);
            acc[3][0] = fma2(wp3, cp0, acc[3][0]);
            acc[3][1] = fma2(wp3, cp1, acc[3][1]);
            acc[3][2] = fma2(wp3, cp2, acc[3][2]);
            acc[3][3] = fma2(wp3, cp3, acc[3][3]);
        }
    }

    // ---- epilogue: full-K accs, add bias, store ----
    #pragma unroll
    for (int j = 0; j < 4; j++) {
        int o0 = og * 8 + 2 * j;
        float bv0 = __ldg(bias + o0);
        float bv1 = __ldg(bias + o0 + 1);
        float4 re, ro;
        float2 v;
        v = unpack2(acc[j][0]); re.x = v.x + bv0; ro.x = v.y + bv1;
        v = unpack2(acc[j][1]); re.y = v.x + bv0; ro.y = v.y + bv1;
        v = unpack2(acc[j][2]); re.z = v.x + bv0; ro.z = v.y + bv1;
        v = unpack2(acc[j][3]); re.w = v.x + bv0; ro.w = v.y + bv1;
        size_t base = (size_t)(b * OOUT + o0) * PLANE + y * HW + lane * 4;
        *(float4*)(out + base)         = re;
        *(float4*)(out + base + PLANE) = ro;
    }
}

extern "C" void kernel_launch(void* const* d_in, const int* in_sizes, int n_in,
                              void* d_out, int out_size)
{
    const float* input  = (const float*)d_in[0];
    // d_in[1] = depth, unused by the reference computation
    const float* offset = (const float*)d_in[2];
    const float* mask   = (const float*)d_in[3];
    const float* weight = (const float*)d_in[4];
    const float* bias   = (const float*)d_in[5];
    float* out = (float*)d_out;

    cudaFuncSetAttribute(ddc_main,
                         cudaFuncAttributeMaxDynamicSharedMemorySize, SMEM_TOTAL);

    k_nhwc<<<512, 256>>>(input);
    k_prep<<<(OOUT * CKTOT + 255) / 256, 256>>>(weight);
    ddc_main<<<512, NTHREADS, SMEM_TOTAL>>>(offset, mask, bias, out);
}

// round 10
// speedup vs baseline: 1.4643x; 1.4643x over previous
#include <cuda_runtime.h>
#include <cstdint>

// DepthDeformConv: modulated deformable conv 3x3, s=1, p=1, d=1.
// B=4, C=64, H=W=128, O=64, K=9, fp32. Output (4,64,128,128) fp32.
//
// K0 (k_nhwc): repack input NCHW -> NHWC8: g_in8[b][g][y*128+x][8].
// K1 (k_prep): permute weights: g_wt[(cc*72 + k*8 + cl)*64 + o].
// K2 (ddc_main): one block per (b,y); 256 threads; 2 blocks/SM.
//   - META (once): 1152 (k,pix) jobs -> short4 indices + float4 fused weights
//   - SOFTWARE PIPELINE over 8 chunks (8 ch x 9 k = 72 col rows), double-
//     buffered col: each loop iteration interleaves one gather iter for
//     chunk c+1 (dense 4xLDG.64 taps -> swizzled col[nxt]) with 4 FMA rows
//     of chunk c (col[cur]); LDG latency hides under the FMA stream.
//     One __syncthreads per chunk.
//   - FMA: warp = 8 outputs x 128 pix, full-K accum in regs (acc = 32 regs);
//     weights via warp-uniform __ldg from permuted g_wt (L1-resident).
//   - epilogue: bias + STG.128 (no reduction).

#define HW 128
#define PLANE 16384
#define CIN 64
#define OOUT 64
#define CKTOT 576
#define NJOBS 1152
#define RPC 72
#define NCHUNK 8
#define NTHREADS 256
#define COLBUF (RPC * HW)               // 9216 floats

#define OFF_MI 73728                    // col double buf: [0, 73728)
#define OFF_MW (OFF_MI + 9216)          // 82944
#define SMEM_TOTAL (OFF_MW + 18432)     // 101376

typedef unsigned long long ull;

__device__ float g_in8[4 * 8 * PLANE * 8];   // 16 MB
__device__ float g_wt[CKTOT * OOUT];

__device__ __forceinline__ ull pack2(float lo, float hi) {
    ull d;
    asm("mov.b64 %0, {%1, %2};" : "=l"(d) : "f"(lo), "f"(hi));
    return d;
}
__device__ __forceinline__ float2 unpack2(ull v) {
    float2 r;
    asm("mov.b64 {%0, %1}, %2;" : "=f"(r.x), "=f"(r.y) : "l"(v));
    return r;
}
__device__ __forceinline__ ull fma2(ull a, ull b, ull c) {
    ull d;
    asm("fma.rn.f32x2 %0, %1, %2, %3;" : "=l"(d) : "l"(a), "l"(b), "l"(c));
    return d;
}

// ---------------- K0: NCHW -> NHWC8 ----------------
__global__ __launch_bounds__(256) void k_nhwc(const float* __restrict__ in) {
    __shared__ float t[64][129];
    const int bid = blockIdx.x;
    const int y = bid & 127, b = bid >> 7;
    const int tid = threadIdx.x;
    const float* ib = in + (size_t)b * CIN * PLANE + y * HW;
    #pragma unroll 8
    for (int it = 0; it < 32; it++) {
        int i = tid + it * 256;
        int c = i >> 7, x = i & 127;
        t[c][x] = __ldg(ib + c * PLANE + x);
    }
    __syncthreads();
    #pragma unroll 8
    for (int it = 0; it < 32; it++) {
        int i = tid + it * 256;
        int cl = i & 7, x = (i >> 3) & 127, g = i >> 10;
        g_in8[(((size_t)(b * 8 + g)) * PLANE + y * HW + x) * 8 + cl] = t[g * 8 + cl][x];
    }
}

// ---------------- K1: weight permute ----------------
__global__ __launch_bounds__(256) void k_prep(const float* __restrict__ w) {
    int idx = blockIdx.x * 256 + threadIdx.x;
    if (idx >= OOUT * CKTOT) return;
    int o = idx / CKTOT, rem = idx - o * CKTOT;
    int c = rem / 9, k = rem - c * 9;
    int cc = c >> 3, cl = c & 7;
    g_wt[(cc * RPC + k * 8 + cl) * OOUT + o] = w[idx];
}

// ---------------- K2: main ----------------
extern __shared__ char smraw[];

__global__ __launch_bounds__(NTHREADS, 2)
void ddc_main(const float* __restrict__ offset,
              const float* __restrict__ mask,
              const float* __restrict__ bias,
              float* __restrict__ out)
{
    float*  col    = (float*)smraw;              // 2 x [72][128] swizzled
    short4* meta_i = (short4*)(smraw + OFF_MI);
    float4* meta_w = (float4*)(smraw + OFF_MW);

    const int tid = threadIdx.x;
    const int bid = blockIdx.x;
    const int y = bid & 127;
    const int b = bid >> 7;
    const int wid  = tid >> 5;
    const int lane = tid & 31;
    const int og   = wid;          // o-group: 8 outputs, o base = og*8
    const int grp  = tid >> 2;     // gather group 0..63
    const int p    = tid & 3;      // channel pair within group

    // ---- META: 1152 jobs, once per block ----
    for (int i = tid; i < NJOBS; i += NTHREADS) {
        int pix = i & 127;
        int k   = i >> 7;
        int ky  = k / 3;
        int kx  = k - ky * 3;

        int ob = ((b * 18 + 2 * k) * HW + y) * HW + pix;
        float oy = __ldg(offset + ob);
        float ox = __ldg(offset + ob + PLANE);
        float m  = __ldg(mask + ((b * 9 + k) * HW + y) * HW + pix);

        float py = (float)(y - 1 + ky) + oy;
        float px = (float)(pix - 1 + kx) + ox;
        float y0f = floorf(py), x0f = floorf(px);
        int y0 = (int)y0f, x0 = (int)x0f;
        float wy = py - y0f, wx = px - x0f;
        int y1 = y0 + 1, x1 = x0 + 1;

        float vy0 = (y0 >= 0 && y0 < HW) ? 1.f : 0.f;
        float vy1 = (y1 >= 0 && y1 < HW) ? 1.f : 0.f;
        float vx0 = (x0 >= 0 && x0 < HW) ? 1.f : 0.f;
        float vx1 = (x1 >= 0 && x1 < HW) ? 1.f : 0.f;
        int yc0 = min(max(y0, 0), HW - 1);
        int yc1 = min(max(y1, 0), HW - 1);
        int xc0 = min(max(x0, 0), HW - 1);
        int xc1 = min(max(x1, 0), HW - 1);

        float4 w;
        w.x = (1.f - wy) * (1.f - wx) * m * vy0 * vx0;
        w.y = (1.f - wy) * wx         * m * vy0 * vx1;
        w.z = wy         * (1.f - wx) * m * vy1 * vx0;
        w.w = wy         * wx         * m * vy1 * vx1;

        meta_i[i] = make_short4((short)(yc0 * HW + xc0), (short)(yc0 * HW + xc1),
                                (short)(yc1 * HW + xc0), (short)(yc1 * HW + xc1));
        meta_w[i] = w;
    }
    __syncthreads();

    // acc[j][q]: o-pair j (o = og*8 + 2j, +2j+1), pixel q (pix = lane*4+q)
    ull acc[4][4];
    #pragma unroll
    for (int j = 0; j < 4; j++)
        #pragma unroll
        for (int q = 0; q < 4; q++) acc[j][q] = 0ULL;

    // ---- prologue: gather chunk 0 into buf 0 ----
    {
        const float2* nb = (const float2*)g_in8 + ((size_t)(b * 8 + 0)) * PLANE * 4;
        #pragma unroll 2
        for (int j = grp; j < NJOBS; j += 64) {
            short4 mi = meta_i[j];
            float4 mw = meta_w[j];
            float2 t00 = __ldg(nb + ((int)mi.x << 2) + p);
            float2 t01 = __ldg(nb + ((int)mi.y << 2) + p);
            float2 t10 = __ldg(nb + ((int)mi.z << 2) + p);
            float2 t11 = __ldg(nb + ((int)mi.w << 2) + p);
            float vx_ = mw.x * t00.x + mw.y * t01.x + mw.z * t10.x + mw.w * t11.x;
            float vy_ = mw.x * t00.y + mw.y * t01.y + mw.z * t10.y + mw.w * t11.y;
            int r   = (j >> 7) * 8 + 2 * p;
            int psw = (j & 127) ^ (p << 3);
            col[r * HW + psw]       = vx_;
            col[(r + 1) * HW + psw] = vy_;
        }
    }
    __syncthreads();

    // ---- pipelined main loop ----
    for (int cc = 0; cc < NCHUNK; cc++) {
        float* cur = col + (cc & 1) * COLBUF;
        float* nxt = col + ((cc + 1) & 1) * COLBUF;
        const float2* nb = (const float2*)g_in8 + ((size_t)(b * 8 + cc + 1)) * PLANE * 4;
        const float4* wbase = (const float4*)(g_wt + (size_t)cc * RPC * OOUT + og * 8);
        const bool more = (cc + 1 < NCHUNK);

        #pragma unroll 2
        for (int u = 0; u < 18; u++) {
            // --- one gather iteration for chunk cc+1 (independent of FMA) ---
            if (more) {
                int j = grp + u * 64;
                short4 mi = meta_i[j];
                float4 mw = meta_w[j];
                float2 t00 = __ldg(nb + ((int)mi.x << 2) + p);
                float2 t01 = __ldg(nb + ((int)mi.y << 2) + p);
                float2 t10 = __ldg(nb + ((int)mi.z << 2) + p);
                float2 t11 = __ldg(nb + ((int)mi.w << 2) + p);
                float vx_ = mw.x * t00.x + mw.y * t01.x + mw.z * t10.x + mw.w * t11.x;
                float vy_ = mw.x * t00.y + mw.y * t01.y + mw.z * t10.y + mw.w * t11.y;
                int r   = (j >> 7) * 8 + 2 * p;
                int psw = (j & 127) ^ (p << 3);
                nxt[r * HW + psw]       = vx_;
                nxt[(r + 1) * HW + psw] = vy_;
            }
            // --- 4 FMA rows of chunk cc ---
            #pragma unroll
            for (int v = 0; v < 4; v++) {
                int row = u * 4 + v;
                int sw = (((unsigned)row >> 1) & 3) << 3;
                float4 cq = *(const float4*)(cur + row * HW + ((lane * 4) ^ sw));
                ull cp0 = pack2(cq.x, cq.x);
                ull cp1 = pack2(cq.y, cq.y);
                ull cp2 = pack2(cq.z, cq.z);
                ull cp3 = pack2(cq.w, cq.w);
                float4 wq0 = __ldg(wbase + row * 16);       // o pairs 0,1
                float4 wq1 = __ldg(wbase + row * 16 + 1);   // o pairs 2,3
                ull wp0 = pack2(wq0.x, wq0.y);
                ull wp1 = pack2(wq0.z, wq0.w);
                ull wp2 = pack2(wq1.x, wq1.y);
                ull wp3 = pack2(wq1.z, wq1.w);
                acc[0][0] = fma2(wp0, cp0, acc[0][0]);
                acc[0][1] = fma2(wp0, cp1, acc[0][1]);
                acc[0][2] = fma2(wp0, cp2, acc[0][2]);
                acc[0][3] = fma2(wp0, cp3, acc[0][3]);
                acc[1][0] = fma2(wp1, cp0, acc[1][0]);
                acc[1][1] = fma2(wp1, cp1, acc[1][1]);
                acc[1][2] = fma2(wp1, cp2, acc[1][2]);
                acc[1][3] = fma2(wp1, cp3, acc[1][3]);
                acc[2][0] = fma2(wp2, cp0, acc[2][0]);
                acc[2][1] = fma2(wp2, cp1, acc[2][1]);
                acc[2][2] = fma2(wp2, cp2, acc[2][2]);
                acc[2][3] = fma2(wp2, cp3, acc[2][3]);
                acc[3][0] = fma2(wp3, cp0, acc[3][0]);
                acc[3][1] = fma2(wp3, cp1, acc[3][1]);
                acc[3][2] = fma2(wp3, cp2, acc[3][2]);
                acc[3][3] = fma2(wp3, cp3, acc[3][3]);
            }
        }
        __syncthreads();   // nxt fully written, cur fully consumed
    }

    // ---- epilogue: full-K accs, add bias, store ----
    #pragma unroll
    for (int j = 0; j < 4; j++) {
        int o0 = og * 8 + 2 * j;
        float bv0 = __ldg(bias + o0);
        float bv1 = __ldg(bias + o0 + 1);
        float4 re, ro;
        float2 v;
        v = unpack2(acc[j][0]); re.x = v.x + bv0; ro.x = v.y + bv1;
        v = unpack2(acc[j][1]); re.y = v.x + bv0; ro.y = v.y + bv1;
        v = unpack2(acc[j][2]); re.z = v.x + bv0; ro.z = v.y + bv1;
        v = unpack2(acc[j][3]); re.w = v.x + bv0; ro.w = v.y + bv1;
        size_t base = (size_t)(b * OOUT + o0) * PLANE + y * HW + lane * 4;
        *(float4*)(out + base)         = re;
        *(float4*)(out + base + PLANE) = ro;
    }
}

extern "C" void kernel_launch(void* const* d_in, const int* in_sizes, int n_in,
                              void* d_out, int out_size)
{
    const float* input  = (const float*)d_in[0];
    // d_in[1] = depth, unused by the reference computation
    const float* offset = (const float*)d_in[2];
    const float* mask   = (const float*)d_in[3];
    const float* weight = (const float*)d_in[4];
    const float* bias   = (const float*)d_in[5];
    float* out = (float*)d_out;

    cudaFuncSetAttribute(ddc_main,
                         cudaFuncAttributeMaxDynamicSharedMemorySize, SMEM_TOTAL);

    k_nhwc<<<512, 256>>>(input);
    k_prep<<<(OOUT * CKTOT + 255) / 256, 256>>>(weight);
    ddc_main<<<512, NTHREADS, SMEM_TOTAL>>>(offset, mask, bias, out);
}